// round 12
// baseline (speedup 1.0000x reference)
#include <cuda_runtime.h>
#include <cstdint>

// ---------------------------------------------------------------------------
// Fused: h = x @ w^T + b ; instance-norm over OUT ; out = (norm(h)+y)*y
// Single GEMM pass + Gram-identity row stats.
// R12 = R11 (208.8us: coalesced epilogue + fragment-major w) + cross-chunk
// b-prefetch: compute_chunk takes the first b-fragment set preloaded and
// prefetches the NEXT chunk's j=0 fragments during its last iteration, so the
// next GEMM's operands are in flight while this chunk's epilogue runs.
// Removes the per-chunk L2-latency serialization at each chunk start.
// ---------------------------------------------------------------------------

#define DEVINL __device__ __forceinline__

static constexpr int IN      = 128;
static constexpr int OUT     = 2048;
static constexpr int MTILE   = 64;
static constexpr int NCHUNK  = 128;
static constexpr int NCHUNKS = OUT / NCHUNK;   // 16
static constexpr int THREADS = 256;            // 8 warps: 2m x 4n
static constexpr int TS      = 132;            // x tile row stride (floats)
static constexpr int SSTR    = 40;             // stage tile row stride (floats)

// SMEM layout (floats)
static constexpr int X_OFF     = 0;                      // 64 x 132
static constexpr int STAGE_OFF = X_OFF + MTILE * TS;     // 8 warps x 32 x 40
static constexpr int MEAN_OFF  = STAGE_OFF + 8 * 32 * SSTR;
static constexpr int DOTC_OFF  = MEAN_OFF + MTILE;
static constexpr int SQ_OFF    = DOTC_OFF + MTILE;
static constexpr int ISTD_OFF  = SQ_OFF + MTILE;
static constexpr int TOTAL_F   = ISTD_OFF + MTILE;       // ~76 KB

// ---- device scratch ----
__device__ __align__(16) float g_wp[OUT * IN];   // fragment-major truncated w
__device__ __align__(16) float g_G[IN * IN];     // Gram, fragment-major
__device__ __align__(16) float g_c[IN];          // permuted (x-layout order)
__device__ __align__(16) float g_sw[IN];         // permuted
__device__ float g_db[2];

DEVINL float tf32_trunc(float f) {
    return __uint_as_float(__float_as_uint(f) & 0xFFFFE000u);
}
DEVINL uint32_t f2tf32(float f) {
    uint32_t r;
    asm("cvt.rna.tf32.f32 %0, %1;" : "=r"(r) : "f"(f));
    return r;
}

DEVINL void mma_tf32(float* c, uint32_t a0, uint32_t a1, uint32_t a2, uint32_t a3,
                     uint32_t b0, uint32_t b1) {
    asm volatile(
        "mma.sync.aligned.m16n8k8.row.col.f32.tf32.tf32.f32 "
        "{%0,%1,%2,%3}, {%4,%5,%6,%7}, {%8,%9}, {%0,%1,%2,%3};"
        : "+f"(c[0]), "+f"(c[1]), "+f"(c[2]), "+f"(c[3])
        : "r"(a0), "r"(a1), "r"(a2), "r"(a3), "r"(b0), "r"(b1));
}

// Column permutation (x smem layout): logical k -> packed index in 128-float row.
DEVINL int permc(int k) {
    int tg = k & 3, h = (k >> 2) & 1, s = k >> 3;
    int i = 2 * s + h;
    return ((i >> 2) * 4 + tg) * 4 + (i & 3);
}
// x SMEM float offset of logical (row, k) with skew slot' = (sl+3r)&31.
DEVINL int xoff_perm(int r, int k) {
    int p = permc(k);
    int sl = p >> 2;
    int seg = (sl + 3 * r) & 31;
    return r * TS + seg * 4 + (p & 3);
}
// Fragment-major gmem float offset for (row, packed index p) within a 128-row
// chunk-local space.
DEVINL int wfrag_off(int row, int p) {
    int sl = p >> 2, pos = p & 3;
    int j = sl >> 2, tg = sl & 3;
    return (row >> 3) * 1024 + j * 128 + (((row & 7) * 4 + tg) * 4) + pos;
}

// ---------------- precompute kernels ----------------

__global__ void zero_scratch_kernel() {
    int i = blockIdx.x * blockDim.x + threadIdx.x;
    if (i < IN * IN) g_G[i] = 0.0f;
    if (i < IN) { g_c[i] = 0.0f; g_sw[i] = 0.0f; }
    if (i < 2)  g_db[i] = 0.0f;
}

__global__ __launch_bounds__(256, 1)
void gram_kernel(const float* __restrict__ w, const float* __restrict__ b) {
    __shared__ float ws[32][IN];
    __shared__ float bs[32];
    const int tid   = threadIdx.x;
    const int jbase = blockIdx.x * 32;

    #pragma unroll
    for (int it = 0; it < 4; ++it) {
        int i  = it * 256 + tid;
        int j  = i >> 5;
        int c4 = (i & 31) * 4;
        float4 v = *reinterpret_cast<const float4*>(w + (size_t)(jbase + j) * IN + c4);
        ws[j][c4 + 0] = tf32_trunc(v.x);
        ws[j][c4 + 1] = tf32_trunc(v.y);
        ws[j][c4 + 2] = tf32_trunc(v.z);
        ws[j][c4 + 3] = tf32_trunc(v.w);
    }
    if (tid < 32) bs[tid] = b[jbase + tid];
    __syncthreads();

    // Emit fragment-major w rows.
    #pragma unroll
    for (int it = 0; it < 16; ++it) {
        int i = it * 256 + tid;
        int j = i >> 7;                     // local row
        int q = i & 127;                    // packed index p
        int sl = q >> 2, pos = q & 3;
        int i2 = (sl >> 2) * 4 + pos;
        int k  = 8 * (i2 >> 1) + 4 * (i2 & 1) + (sl & 3);   // logical k
        int R  = jbase + j;                 // global row
        g_wp[(size_t)(R >> 7) * (128 * IN) + wfrag_off(R & 127, q)] = ws[j][k];
    }

    const int k     = tid & 127;
    const int lbase = (tid >> 7) * 64;
    float acc[64];
    #pragma unroll
    for (int l = 0; l < 64; ++l) acc[l] = 0.0f;
    float ck = 0.0f, swk = 0.0f;

    for (int j = 0; j < 32; ++j) {
        float wk = ws[j][k];
        #pragma unroll
        for (int l = 0; l < 64; ++l) acc[l] += wk * ws[j][lbase + l];
        ck  += bs[j] * wk;
        swk += wk;
    }
    #pragma unroll
    for (int l = 0; l < 64; ++l)
        atomicAdd(&g_G[wfrag_off(k, permc(lbase + l))], acc[l]);
    if (tid < IN) {
        atomicAdd(&g_c[permc(k)], ck);
        atomicAdd(&g_sw[permc(k)], swk);
    }
    if (tid < 32) {
        atomicAdd(&g_db[0], bs[tid] * bs[tid]);
        atomicAdd(&g_db[1], bs[tid]);
    }
}

// ---------------- main kernel ----------------

DEVINL void load_x_tile(float* dst, const float* __restrict__ g, int tid) {
    #pragma unroll
    for (int it = 0; it < (MTILE * 32) / THREADS; ++it) {
        int i  = it * THREADS + tid;
        int r  = i >> 5;
        int c4 = (i & 31) * 4;
        float4 v = *reinterpret_cast<const float4*>(g + (size_t)r * IN + c4);
        float vv[4] = {v.x, v.y, v.z, v.w};
        #pragma unroll
        for (int e = 0; e < 4; ++e)
            dst[xoff_perm(r, c4 + e)] = __uint_as_float(f2tf32(vv[e]));
    }
}

DEVINL void preload_b(const float* __restrict__ wg, int rg0, int lane4,
                      float4 bfn[4]) {
    #pragma unroll
    for (int nt = 0; nt < 4; ++nt)
        bfn[nt] = __ldg(reinterpret_cast<const float4*>(
                        wg + (rg0 + nt) * 1024 + lane4));
}

// Warp-tile 32x32 GEMM, K=128. a: LDS.128 (conflict-free). b: LDG.128 from
// fragment-major gmem. bfn enters holding this chunk's j=0 fragments and
// LEAVES holding wg_next's j=0 fragments (cross-chunk pipeline bridge).
DEVINL void compute_chunk(const float* __restrict__ xs, const float* __restrict__ wg,
                          const float* __restrict__ wg_next,
                          int m0, int n0, int g, int tig, int lane4,
                          float4 bfn[4], float acc[2][4][4]) {
    #pragma unroll
    for (int mt = 0; mt < 2; ++mt)
        #pragma unroll
        for (int nt = 0; nt < 4; ++nt)
            #pragma unroll
            for (int q = 0; q < 4; ++q)
                acc[mt][nt][q] = 0.0f;

    const int rg0 = n0 >> 3;

    #pragma unroll
    for (int j = 0; j < 8; ++j) {
        float4 bf[4];
        #pragma unroll
        for (int nt = 0; nt < 4; ++nt) bf[nt] = bfn[nt];
        if (j < 7) {
            #pragma unroll
            for (int nt = 0; nt < 4; ++nt)
                bfn[nt] = __ldg(reinterpret_cast<const float4*>(
                                wg + (rg0 + nt) * 1024 + (j + 1) * 128 + lane4));
        } else {
            // bridge: prefetch the NEXT chunk's j=0 fragments; they arrive
            // while this chunk's stage+epilogue executes.
            #pragma unroll
            for (int nt = 0; nt < 4; ++nt)
                bfn[nt] = __ldg(reinterpret_cast<const float4*>(
                                wg_next + (rg0 + nt) * 1024 + lane4));
        }

        float4 af[2][2];
        #pragma unroll
        for (int mt = 0; mt < 2; ++mt) {
            const int r1 = m0 + mt * 16 + g;
            const int r2 = r1 + 8;
            af[mt][0] = *reinterpret_cast<const float4*>(
                            xs + r1 * TS + (((j * 4 + tig + 3 * r1) & 31) * 4));
            af[mt][1] = *reinterpret_cast<const float4*>(
                            xs + r2 * TS + (((j * 4 + tig + 3 * r2) & 31) * 4));
        }

        #pragma unroll
        for (int mt = 0; mt < 2; ++mt)
            #pragma unroll
            for (int nt = 0; nt < 4; ++nt)
                mma_tf32(acc[mt][nt],
                         __float_as_uint(af[mt][0].x), __float_as_uint(af[mt][1].x),
                         __float_as_uint(af[mt][0].y), __float_as_uint(af[mt][1].y),
                         __float_as_uint(bf[nt].x),   __float_as_uint(bf[nt].y));
        #pragma unroll
        for (int mt = 0; mt < 2; ++mt)
            #pragma unroll
            for (int nt = 0; nt < 4; ++nt)
                mma_tf32(acc[mt][nt],
                         __float_as_uint(af[mt][0].z), __float_as_uint(af[mt][1].z),
                         __float_as_uint(af[mt][0].w), __float_as_uint(af[mt][1].w),
                         __float_as_uint(bf[nt].z),   __float_as_uint(bf[nt].w));
    }
}

__global__ __launch_bounds__(THREADS, 2)
void fused_lin_inorm_kernel(const float* __restrict__ x,
                            const float* __restrict__ y,
                            const float* __restrict__ lb,
                            const float* __restrict__ nw,
                            const float* __restrict__ nb,
                            float* __restrict__ out) {
    __shared__ float sm[TOTAL_F];
    const int tid  = threadIdx.x;
    const int wid  = tid >> 5;
    const int lane = tid & 31;
    const int g    = lane >> 2;
    const int tig  = lane & 3;
    const int m0   = (wid >> 2) * 32;
    const int n0   = (wid & 3) * 32;
    const int lane4 = lane * 4;
    const size_t row0 = (size_t)blockIdx.x * MTILE;

    float* xs = sm + X_OFF;
    float* st = sm + STAGE_OFF + wid * (32 * SSTR);   // warp-private stage

    if (tid < MTILE) sm[SQ_OFF + tid] = 0.0f;
    load_x_tile(xs, x + row0 * IN, tid);
    __syncthreads();

    if (tid < MTILE) {
        const int r = tid;
        float dm = 0.0f, dc = 0.0f;
        #pragma unroll 8
        for (int sl = 0; sl < 32; ++sl) {
            int seg = (sl + 3 * r) & 31;
            float4 xv = *reinterpret_cast<const float4*>(xs + r * TS + seg * 4);
            float4 sv = *reinterpret_cast<const float4*>(g_sw + sl * 4);
            float4 cv = *reinterpret_cast<const float4*>(g_c + sl * 4);
            dm += xv.x * sv.x + xv.y * sv.y + xv.z * sv.z + xv.w * sv.w;
            dc += xv.x * cv.x + xv.y * cv.y + xv.z * cv.z + xv.w * cv.w;
        }
        sm[MEAN_OFF + r] = (dm + g_db[1]) * (1.0f / OUT);
        sm[DOTC_OFF + r] = dc;
    }

    // Prime the b pipeline with the stats chunk's j=0 fragments.
    float4 bfn[4];
    preload_b(g_G, n0 >> 3, lane4, bfn);

    // ---- stats chunk: Z = x' @ G ; rsq = sum Z .* x' per row ----
    {
        float acc[2][4][4];
        compute_chunk(xs, g_G, g_wp /* next = chunk 0 */,
                      m0, n0, g, tig, lane4, bfn, acc);

        float rsq[4] = {0.f, 0.f, 0.f, 0.f};
        #pragma unroll
        for (int mt = 0; mt < 2; ++mt)
            #pragma unroll
            for (int h = 0; h < 2; ++h) {
                const int r = m0 + mt * 16 + h * 8 + g;
                #pragma unroll
                for (int nt = 0; nt < 4; ++nt)
                    #pragma unroll
                    for (int p = 0; p < 2; ++p) {
                        int col = n0 + nt * 8 + tig * 2 + p;
                        rsq[mt * 2 + h] += acc[mt][nt][h * 2 + p] * xs[xoff_perm(r, col)];
                    }
            }
        #pragma unroll
        for (int j = 0; j < 4; ++j) {
            rsq[j] += __shfl_xor_sync(0xffffffffu, rsq[j], 1);
            rsq[j] += __shfl_xor_sync(0xffffffffu, rsq[j], 2);
        }
        if (tig == 0) {
            #pragma unroll
            for (int j = 0; j < 4; ++j) {
                int r = m0 + (j >> 1) * 16 + (j & 1) * 8 + g;
                atomicAdd(&sm[SQ_OFF + r], rsq[j]);
            }
        }
    }
    __syncthreads();

    if (tid < MTILE) {
        float sumsq = sm[SQ_OFF + tid] + 2.0f * sm[DOTC_OFF + tid] + g_db[0];
        float mean  = sm[MEAN_OFF + tid];
        float var   = sumsq * (1.0f / OUT) - mean * mean;
        sm[ISTD_OFF + tid] = rsqrtf(var + 1e-5f);
    }
    __syncthreads();

    // Per-lane epilogue row constants (iteration j covers rows j*4 + (lane>>3)).
    const int rl = lane >> 3;       // 0..3
    const int cl = (lane & 7) * 4;  // 0,4,...,28
    float meanv[8], istdv[8];
    #pragma unroll
    for (int j = 0; j < 8; ++j) {
        int r = m0 + j * 4 + rl;
        meanv[j] = sm[MEAN_OFF + r];
        istdv[j] = sm[ISTD_OFF + r];
    }

    // ---------------- main loop: 16 chunks, NO CTA barriers ----------------
    #pragma unroll 1
    for (int ch = 0; ch < NCHUNKS; ++ch) {
        const float* wg      = g_wp + (size_t)ch * NCHUNK * IN;
        const float* wg_next = g_wp + (size_t)(ch < NCHUNKS - 1 ? ch + 1 : ch) * NCHUNK * IN;

        float acc[2][4][4];
        compute_chunk(xs, wg, wg_next, m0, n0, g, tig, lane4, bfn, acc);

        // Stage the 32x32 acc tile into warp-private smem (conflict-free).
        #pragma unroll
        for (int mt = 0; mt < 2; ++mt)
            #pragma unroll
            for (int h = 0; h < 2; ++h)
                #pragma unroll
                for (int nt = 0; nt < 4; ++nt) {
                    float2 v = make_float2(acc[mt][nt][h * 2 + 0], acc[mt][nt][h * 2 + 1]);
                    *reinterpret_cast<float2*>(
                        st + (mt * 16 + h * 8 + g) * SSTR + nt * 8 + tig * 2) = v;
                }
        __syncwarp();

        // Coalesced readback + fused epilogue (float4, 4 lines/instr).
        const int cbase = ch * NCHUNK + n0;
        float4 lbv = __ldg(reinterpret_cast<const float4*>(lb + cbase + cl));
        float4 nwv = __ldg(reinterpret_cast<const float4*>(nw + cbase + cl));
        float4 nbv = __ldg(reinterpret_cast<const float4*>(nb + cbase + cl));

        #pragma unroll
        for (int j = 0; j < 8; ++j) {
            const int r = j * 4 + rl;
            float4 v = *reinterpret_cast<const float4*>(st + r * SSTR + cl);
            const size_t grow = row0 + (size_t)(m0 + r);
            float4 yv = __ldg(reinterpret_cast<const float4*>(y + grow * OUT + cbase + cl));
            const float mean = meanv[j], istd = istdv[j];
            float4 ov;
            float nm;
            nm = ((v.x + lbv.x) - mean) * istd * nwv.x + nbv.x; ov.x = (nm + yv.x) * yv.x;
            nm = ((v.y + lbv.y) - mean) * istd * nwv.y + nbv.y; ov.y = (nm + yv.y) * yv.y;
            nm = ((v.z + lbv.z) - mean) * istd * nwv.z + nbv.z; ov.z = (nm + yv.z) * yv.z;
            nm = ((v.w + lbv.w) - mean) * istd * nwv.w + nbv.w; ov.w = (nm + yv.w) * yv.w;
            *reinterpret_cast<float4*>(out + grow * OUT + cbase + cl) = ov;
        }
        __syncwarp();   // stage buffer reusable next chunk
    }
}

extern "C" void kernel_launch(void* const* d_in, const int* in_sizes, int n_in,
                              void* d_out, int out_size) {
    (void)n_in; (void)out_size;
    const float* x  = (const float*)d_in[0];
    const float* y  = (const float*)d_in[1];
    const float* w  = (const float*)d_in[2];
    const float* lb = (const float*)d_in[3];
    const float* nw = (const float*)d_in[4];
    const float* nb = (const float*)d_in[5];
    float* out = (float*)d_out;

    const int rows = in_sizes[0] / IN;   // 32768
    const int grid = rows / MTILE;       // 512

    zero_scratch_kernel<<<64, 256>>>();
    gram_kernel<<<OUT / 32, 256>>>(w, lb);
    fused_lin_inorm_kernel<<<grid, THREADS>>>(x, y, lb, nw, nb, out);
}

// round 13
// speedup vs baseline: 1.0529x; 1.0529x over previous
#include <cuda_runtime.h>
#include <cstdint>

// ---------------------------------------------------------------------------
// Fused: h = x @ w^T + b ; instance-norm over OUT ; out = (norm(h)+y)*y
// Single GEMM pass + Gram-identity row stats.
// R13 = R11 (208.8us: coalesced epilogue + fragment-major w; R12 bridge
// reverted) + warp-private y prefetch: each chunk, every warp cp.async's its
// own 32x32 y sub-tile into private smem BEFORE the mma chain (zero register
// cost, smem-destined MLP), then the epilogue reads y from smem. Hides the
// ~600-cycle DRAM y latency that was serializing each chunk's epilogue.
// ---------------------------------------------------------------------------

#define DEVINL __device__ __forceinline__

static constexpr int IN      = 128;
static constexpr int OUT     = 2048;
static constexpr int MTILE   = 64;
static constexpr int NCHUNK  = 128;
static constexpr int NCHUNKS = OUT / NCHUNK;   // 16
static constexpr int THREADS = 256;            // 8 warps: 2m x 4n
static constexpr int TS      = 132;            // x tile row stride (floats)
static constexpr int SSTR    = 40;             // stage tile row stride (floats)

// SMEM layout (floats)
static constexpr int X_OFF     = 0;                      // 64 x 132
static constexpr int STAGE_OFF = X_OFF + MTILE * TS;     // 8 warps x 32 x 40
static constexpr int YBUF_OFF  = STAGE_OFF + 8 * 32 * SSTR;  // 8 warps x 1024
static constexpr int MEAN_OFF  = YBUF_OFF + 8 * 1024;
static constexpr int DOTC_OFF  = MEAN_OFF + MTILE;
static constexpr int SQ_OFF    = DOTC_OFF + MTILE;
static constexpr int ISTD_OFF  = SQ_OFF + MTILE;
static constexpr int TOTAL_F   = ISTD_OFF + MTILE;       // ~106 KB

// ---- device scratch ----
__device__ __align__(16) float g_wp[OUT * IN];   // fragment-major truncated w
__device__ __align__(16) float g_G[IN * IN];     // Gram, fragment-major
__device__ __align__(16) float g_c[IN];          // permuted (x-layout order)
__device__ __align__(16) float g_sw[IN];         // permuted
__device__ float g_db[2];

DEVINL float tf32_trunc(float f) {
    return __uint_as_float(__float_as_uint(f) & 0xFFFFE000u);
}
DEVINL uint32_t f2tf32(float f) {
    uint32_t r;
    asm("cvt.rna.tf32.f32 %0, %1;" : "=r"(r) : "f"(f));
    return r;
}
DEVINL uint32_t smem_u32(const void* p) {
    uint32_t a;
    asm("{ .reg .u64 t; cvta.to.shared.u64 t, %1; cvt.u32.u64 %0, t; }"
        : "=r"(a) : "l"(p));
    return a;
}
DEVINL void cp_async16(uint32_t saddr, const void* g) {
    asm volatile("cp.async.cg.shared.global [%0], [%1], 16;" :: "r"(saddr), "l"(g));
}
#define CP_COMMIT() asm volatile("cp.async.commit_group;" ::: "memory")
#define CP_WAIT0()  asm volatile("cp.async.wait_group 0;" ::: "memory")

DEVINL void mma_tf32(float* c, uint32_t a0, uint32_t a1, uint32_t a2, uint32_t a3,
                     uint32_t b0, uint32_t b1) {
    asm volatile(
        "mma.sync.aligned.m16n8k8.row.col.f32.tf32.tf32.f32 "
        "{%0,%1,%2,%3}, {%4,%5,%6,%7}, {%8,%9}, {%0,%1,%2,%3};"
        : "+f"(c[0]), "+f"(c[1]), "+f"(c[2]), "+f"(c[3])
        : "r"(a0), "r"(a1), "r"(a2), "r"(a3), "r"(b0), "r"(b1));
}

// Column permutation (x smem layout): logical k -> packed index in 128-float row.
DEVINL int permc(int k) {
    int tg = k & 3, h = (k >> 2) & 1, s = k >> 3;
    int i = 2 * s + h;
    return ((i >> 2) * 4 + tg) * 4 + (i & 3);
}
// x SMEM float offset of logical (row, k) with skew slot' = (sl+3r)&31.
DEVINL int xoff_perm(int r, int k) {
    int p = permc(k);
    int sl = p >> 2;
    int seg = (sl + 3 * r) & 31;
    return r * TS + seg * 4 + (p & 3);
}
// Fragment-major gmem float offset for (row, packed index p) within a 128-row
// chunk-local space.
DEVINL int wfrag_off(int row, int p) {
    int sl = p >> 2, pos = p & 3;
    int j = sl >> 2, tg = sl & 3;
    return (row >> 3) * 1024 + j * 128 + (((row & 7) * 4 + tg) * 4) + pos;
}

// ---------------- precompute kernels ----------------

__global__ void zero_scratch_kernel() {
    int i = blockIdx.x * blockDim.x + threadIdx.x;
    if (i < IN * IN) g_G[i] = 0.0f;
    if (i < IN) { g_c[i] = 0.0f; g_sw[i] = 0.0f; }
    if (i < 2)  g_db[i] = 0.0f;
}

__global__ __launch_bounds__(256, 1)
void gram_kernel(const float* __restrict__ w, const float* __restrict__ b) {
    __shared__ float ws[32][IN];
    __shared__ float bs[32];
    const int tid   = threadIdx.x;
    const int jbase = blockIdx.x * 32;

    #pragma unroll
    for (int it = 0; it < 4; ++it) {
        int i  = it * 256 + tid;
        int j  = i >> 5;
        int c4 = (i & 31) * 4;
        float4 v = *reinterpret_cast<const float4*>(w + (size_t)(jbase + j) * IN + c4);
        ws[j][c4 + 0] = tf32_trunc(v.x);
        ws[j][c4 + 1] = tf32_trunc(v.y);
        ws[j][c4 + 2] = tf32_trunc(v.z);
        ws[j][c4 + 3] = tf32_trunc(v.w);
    }
    if (tid < 32) bs[tid] = b[jbase + tid];
    __syncthreads();

    // Emit fragment-major w rows.
    #pragma unroll
    for (int it = 0; it < 16; ++it) {
        int i = it * 256 + tid;
        int j = i >> 7;                     // local row
        int q = i & 127;                    // packed index p
        int sl = q >> 2, pos = q & 3;
        int i2 = (sl >> 2) * 4 + pos;
        int k  = 8 * (i2 >> 1) + 4 * (i2 & 1) + (sl & 3);   // logical k
        int R  = jbase + j;                 // global row
        g_wp[(size_t)(R >> 7) * (128 * IN) + wfrag_off(R & 127, q)] = ws[j][k];
    }

    const int k     = tid & 127;
    const int lbase = (tid >> 7) * 64;
    float acc[64];
    #pragma unroll
    for (int l = 0; l < 64; ++l) acc[l] = 0.0f;
    float ck = 0.0f, swk = 0.0f;

    for (int j = 0; j < 32; ++j) {
        float wk = ws[j][k];
        #pragma unroll
        for (int l = 0; l < 64; ++l) acc[l] += wk * ws[j][lbase + l];
        ck  += bs[j] * wk;
        swk += wk;
    }
    #pragma unroll
    for (int l = 0; l < 64; ++l)
        atomicAdd(&g_G[wfrag_off(k, permc(lbase + l))], acc[l]);
    if (tid < IN) {
        atomicAdd(&g_c[permc(k)], ck);
        atomicAdd(&g_sw[permc(k)], swk);
    }
    if (tid < 32) {
        atomicAdd(&g_db[0], bs[tid] * bs[tid]);
        atomicAdd(&g_db[1], bs[tid]);
    }
}

// ---------------- main kernel ----------------

DEVINL void load_x_tile(float* dst, const float* __restrict__ g, int tid) {
    #pragma unroll
    for (int it = 0; it < (MTILE * 32) / THREADS; ++it) {
        int i  = it * THREADS + tid;
        int r  = i >> 5;
        int c4 = (i & 31) * 4;
        float4 v = *reinterpret_cast<const float4*>(g + (size_t)r * IN + c4);
        float vv[4] = {v.x, v.y, v.z, v.w};
        #pragma unroll
        for (int e = 0; e < 4; ++e)
            dst[xoff_perm(r, c4 + e)] = __uint_as_float(f2tf32(vv[e]));
    }
}

// Warp-tile 32x32 GEMM, K=128. a: LDS.128 (conflict-free). b: LDG.128 from
// fragment-major gmem (512B contiguous per instr), pipelined j -> j+1.
DEVINL void compute_chunk(const float* __restrict__ xs, const float* __restrict__ wg,
                          int m0, int n0, int g, int tig, int lane4,
                          float acc[2][4][4]) {
    #pragma unroll
    for (int mt = 0; mt < 2; ++mt)
        #pragma unroll
        for (int nt = 0; nt < 4; ++nt)
            #pragma unroll
            for (int q = 0; q < 4; ++q)
                acc[mt][nt][q] = 0.0f;

    const int rg0 = n0 >> 3;

    float4 bfn[4];
    #pragma unroll
    for (int nt = 0; nt < 4; ++nt)
        bfn[nt] = __ldg(reinterpret_cast<const float4*>(
                        wg + (rg0 + nt) * 1024 + lane4));

    #pragma unroll
    for (int j = 0; j < 8; ++j) {
        float4 bf[4];
        #pragma unroll
        for (int nt = 0; nt < 4; ++nt) bf[nt] = bfn[nt];
        if (j < 7) {
            #pragma unroll
            for (int nt = 0; nt < 4; ++nt)
                bfn[nt] = __ldg(reinterpret_cast<const float4*>(
                                wg + (rg0 + nt) * 1024 + (j + 1) * 128 + lane4));
        }

        float4 af[2][2];
        #pragma unroll
        for (int mt = 0; mt < 2; ++mt) {
            const int r1 = m0 + mt * 16 + g;
            const int r2 = r1 + 8;
            af[mt][0] = *reinterpret_cast<const float4*>(
                            xs + r1 * TS + (((j * 4 + tig + 3 * r1) & 31) * 4));
            af[mt][1] = *reinterpret_cast<const float4*>(
                            xs + r2 * TS + (((j * 4 + tig + 3 * r2) & 31) * 4));
        }

        #pragma unroll
        for (int mt = 0; mt < 2; ++mt)
            #pragma unroll
            for (int nt = 0; nt < 4; ++nt)
                mma_tf32(acc[mt][nt],
                         __float_as_uint(af[mt][0].x), __float_as_uint(af[mt][1].x),
                         __float_as_uint(af[mt][0].y), __float_as_uint(af[mt][1].y),
                         __float_as_uint(bf[nt].x),   __float_as_uint(bf[nt].y));
        #pragma unroll
        for (int mt = 0; mt < 2; ++mt)
            #pragma unroll
            for (int nt = 0; nt < 4; ++nt)
                mma_tf32(acc[mt][nt],
                         __float_as_uint(af[mt][0].z), __float_as_uint(af[mt][1].z),
                         __float_as_uint(af[mt][0].w), __float_as_uint(af[mt][1].w),
                         __float_as_uint(bf[nt].z),   __float_as_uint(bf[nt].w));
    }
}

__global__ __launch_bounds__(THREADS, 2)
void fused_lin_inorm_kernel(const float* __restrict__ x,
                            const float* __restrict__ y,
                            const float* __restrict__ lb,
                            const float* __restrict__ nw,
                            const float* __restrict__ nb,
                            float* __restrict__ out) {
    __shared__ float sm[TOTAL_F];
    const int tid  = threadIdx.x;
    const int wid  = tid >> 5;
    const int lane = tid & 31;
    const int g    = lane >> 2;
    const int tig  = lane & 3;
    const int m0   = (wid >> 2) * 32;
    const int n0   = (wid & 3) * 32;
    const int lane4 = lane * 4;
    const size_t row0 = (size_t)blockIdx.x * MTILE;

    float* xs  = sm + X_OFF;
    float* st  = sm + STAGE_OFF + wid * (32 * SSTR);   // warp-private stage
    float* ysm = sm + YBUF_OFF + wid * 1024;           // warp-private y buf
    const uint32_t ybuf_u32 = smem_u32(ysm);

    if (tid < MTILE) sm[SQ_OFF + tid] = 0.0f;
    load_x_tile(xs, x + row0 * IN, tid);
    __syncthreads();

    if (tid < MTILE) {
        const int r = tid;
        float dm = 0.0f, dc = 0.0f;
        #pragma unroll 8
        for (int sl = 0; sl < 32; ++sl) {
            int seg = (sl + 3 * r) & 31;
            float4 xv = *reinterpret_cast<const float4*>(xs + r * TS + seg * 4);
            float4 sv = *reinterpret_cast<const float4*>(g_sw + sl * 4);
            float4 cv = *reinterpret_cast<const float4*>(g_c + sl * 4);
            dm += xv.x * sv.x + xv.y * sv.y + xv.z * sv.z + xv.w * sv.w;
            dc += xv.x * cv.x + xv.y * cv.y + xv.z * cv.z + xv.w * cv.w;
        }
        sm[MEAN_OFF + r] = (dm + g_db[1]) * (1.0f / OUT);
        sm[DOTC_OFF + r] = dc;
    }

    // ---- stats chunk: Z = x' @ G ; rsq = sum Z .* x' per row ----
    {
        float acc[2][4][4];
        compute_chunk(xs, g_G, m0, n0, g, tig, lane4, acc);

        float rsq[4] = {0.f, 0.f, 0.f, 0.f};
        #pragma unroll
        for (int mt = 0; mt < 2; ++mt)
            #pragma unroll
            for (int h = 0; h < 2; ++h) {
                const int r = m0 + mt * 16 + h * 8 + g;
                #pragma unroll
                for (int nt = 0; nt < 4; ++nt)
                    #pragma unroll
                    for (int p = 0; p < 2; ++p) {
                        int col = n0 + nt * 8 + tig * 2 + p;
                        rsq[mt * 2 + h] += acc[mt][nt][h * 2 + p] * xs[xoff_perm(r, col)];
                    }
            }
        #pragma unroll
        for (int j = 0; j < 4; ++j) {
            rsq[j] += __shfl_xor_sync(0xffffffffu, rsq[j], 1);
            rsq[j] += __shfl_xor_sync(0xffffffffu, rsq[j], 2);
        }
        if (tig == 0) {
            #pragma unroll
            for (int j = 0; j < 4; ++j) {
                int r = m0 + (j >> 1) * 16 + (j & 1) * 8 + g;
                atomicAdd(&sm[SQ_OFF + r], rsq[j]);
            }
        }
    }
    __syncthreads();

    if (tid < MTILE) {
        float sumsq = sm[SQ_OFF + tid] + 2.0f * sm[DOTC_OFF + tid] + g_db[0];
        float mean  = sm[MEAN_OFF + tid];
        float var   = sumsq * (1.0f / OUT) - mean * mean;
        sm[ISTD_OFF + tid] = rsqrtf(var + 1e-5f);
    }
    __syncthreads();

    // Per-lane epilogue row constants (iteration j covers rows j*4 + (lane>>3)).
    const int rl = lane >> 3;       // 0..3
    const int cl = (lane & 7) * 4;  // 0,4,...,28
    float meanv[8], istdv[8];
    #pragma unroll
    for (int j = 0; j < 8; ++j) {
        int r = m0 + j * 4 + rl;
        meanv[j] = sm[MEAN_OFF + r];
        istdv[j] = sm[ISTD_OFF + r];
    }

    // ---------------- main loop: 16 chunks, NO CTA barriers ----------------
    #pragma unroll 1
    for (int ch = 0; ch < NCHUNKS; ++ch) {
        const int cbase = ch * NCHUNK + n0;

        // Warp-private y prefetch (zero register cost): lane covers
        // (rloc = lane>>3, c16 = (lane&7)*4); each lane reads exactly the
        // 16B it will consume in the epilogue.
        {
            const float* ysrc = y + (row0 + m0 + rl) * OUT + cbase + cl;
            #pragma unroll
            for (int it = 0; it < 8; ++it)
                cp_async16(ybuf_u32 + (uint32_t)((it * 4 + rl) * 32 + cl) * 4u,
                           ysrc + (size_t)(it * 4) * OUT);
            CP_COMMIT();
        }

        float acc[2][4][4];
        compute_chunk(xs, g_wp + (size_t)ch * NCHUNK * IN, m0, n0, g, tig, lane4, acc);

        // Stage the 32x32 acc tile into warp-private smem (conflict-free).
        #pragma unroll
        for (int mt = 0; mt < 2; ++mt)
            #pragma unroll
            for (int h = 0; h < 2; ++h)
                #pragma unroll
                for (int nt = 0; nt < 4; ++nt) {
                    float2 v = make_float2(acc[mt][nt][h * 2 + 0], acc[mt][nt][h * 2 + 1]);
                    *reinterpret_cast<float2*>(
                        st + (mt * 16 + h * 8 + g) * SSTR + nt * 8 + tig * 2) = v;
                }
        __syncwarp();
        CP_WAIT0();   // y tile resident (each lane reads its own bytes)

        // Coalesced readback + fused epilogue (float4, 4 lines/instr).
        float4 lbv = __ldg(reinterpret_cast<const float4*>(lb + cbase + cl));
        float4 nwv = __ldg(reinterpret_cast<const float4*>(nw + cbase + cl));
        float4 nbv = __ldg(reinterpret_cast<const float4*>(nb + cbase + cl));

        #pragma unroll
        for (int j = 0; j < 8; ++j) {
            const int r = j * 4 + rl;
            float4 v  = *reinterpret_cast<const float4*>(st + r * SSTR + cl);
            float4 yv = *reinterpret_cast<const float4*>(ysm + r * 32 + cl);
            const size_t grow = row0 + (size_t)(m0 + r);
            const float mean = meanv[j], istd = istdv[j];
            float4 ov;
            float nm;
            nm = ((v.x + lbv.x) - mean) * istd * nwv.x + nbv.x; ov.x = (nm + yv.x) * yv.x;
            nm = ((v.y + lbv.y) - mean) * istd * nwv.y + nbv.y; ov.y = (nm + yv.y) * yv.y;
            nm = ((v.z + lbv.z) - mean) * istd * nwv.z + nbv.z; ov.z = (nm + yv.z) * yv.z;
            nm = ((v.w + lbv.w) - mean) * istd * nwv.w + nbv.w; ov.w = (nm + yv.w) * yv.w;
            *reinterpret_cast<float4*>(out + grow * OUT + cbase + cl) = ov;
        }
        __syncwarp();   // stage + y buffers reusable next chunk
    }
}

extern "C" void kernel_launch(void* const* d_in, const int* in_sizes, int n_in,
                              void* d_out, int out_size) {
    (void)n_in; (void)out_size;
    const float* x  = (const float*)d_in[0];
    const float* y  = (const float*)d_in[1];
    const float* w  = (const float*)d_in[2];
    const float* lb = (const float*)d_in[3];
    const float* nw = (const float*)d_in[4];
    const float* nb = (const float*)d_in[5];
    float* out = (float*)d_out;

    const int rows = in_sizes[0] / IN;   // 32768
    const int grid = rows / MTILE;       // 512

    zero_scratch_kernel<<<64, 256>>>();
    gram_kernel<<<OUT / 32, 256>>>(w, lb);
    fused_lin_inorm_kernel<<<grid, THREADS>>>(x, y, lb, nw, nb, out);
}

// round 14
// speedup vs baseline: 1.3440x; 1.2764x over previous
#include <cuda_runtime.h>
#include <cuda_fp16.h>
#include <cstdint>

// ---------------------------------------------------------------------------
// Fused: h = x @ w^T + b ; instance-norm over OUT ; out = (norm(h)+y)*y
// Single GEMM pass + Gram-identity row stats.
// R14 = R11 structure with the GEMM datapath switched tf32 -> fp16 m16n8k16:
// same 10-bit mantissa, half the mma / b-load / a-load instructions, half the
// w bytes (512KB working set -> L1-friendly). x and w are packed fragment-
// major for m16n8k16 so every operand load is one vector instruction.
// Stats use the Gram identity on fp16-rounded w (consistent by construction).
// ---------------------------------------------------------------------------

#define DEVINL __device__ __forceinline__

static constexpr int IN      = 128;
static constexpr int OUT     = 2048;
static constexpr int MTILE   = 64;
static constexpr int NCHUNK  = 128;
static constexpr int NCHUNKS = OUT / NCHUNK;   // 16
static constexpr int THREADS = 256;            // 8 warps: 2m x 4n
static constexpr int SSTR    = 40;             // stage tile row stride (floats)

// SMEM layout (floats)
static constexpr int X_OFF     = 0;                      // 8192 halves = 4096 f
static constexpr int STAGE_OFF = X_OFF + 4096;           // 8 warps x 32 x 40
static constexpr int MEAN_OFF  = STAGE_OFF + 8 * 32 * SSTR;
static constexpr int DOTC_OFF  = MEAN_OFF + MTILE;
static constexpr int SQ_OFF    = DOTC_OFF + MTILE;
static constexpr int ISTD_OFF  = SQ_OFF + MTILE;
static constexpr int TOTAL_F   = ISTD_OFF + MTILE;       // ~58.4 KB

// ---- device scratch ----
__device__ __align__(16) __half g_wh[OUT * IN];  // fragment-major fp16 w
__device__ __align__(16) __half g_Gh[IN * IN];   // Gram, fragment-major fp16
__device__ __align__(16) float  g_Gf[IN * IN];   // Gram fp32 accumulator
__device__ __align__(16) float  g_c[IN];         // natural order
__device__ __align__(16) float  g_sw[IN];        // natural order
__device__ float g_db[2];

DEVINL float f16r(float f) {                     // fp16 round-trip (RNE)
    return __half2float(__float2half_rn(f));
}

DEVINL void mma_f16(float* c, uint32_t a0, uint32_t a1, uint32_t a2, uint32_t a3,
                    uint32_t b0, uint32_t b1) {
    asm volatile(
        "mma.sync.aligned.m16n8k16.row.col.f32.f16.f16.f32 "
        "{%0,%1,%2,%3}, {%4,%5,%6,%7}, {%8,%9}, {%0,%1,%2,%3};"
        : "+f"(c[0]), "+f"(c[1]), "+f"(c[2]), "+f"(c[3])
        : "r"(a0), "r"(a1), "r"(a2), "r"(a3), "r"(b0), "r"(b1));
}

// B-operand fragment-major half offset within a 128-row chunk (r, k in 0..127):
// lane = (r%8)*4 + tig ; uint4 per (row-group, kstep-pair) holds
// [b0_j, b1_j, b0_{j+1}, b1_{j+1}] (2 halves each).
DEVINL int bh_off(int r, int k) {
    int rg = r >> 3, g = r & 7;
    int j = k >> 4, kin = k & 15;
    int hi = kin >> 3;
    int tg = (kin - hi * 8) >> 1;
    int pos = hi * 2 + (kin & 1);
    return rg * 1024 + (j >> 1) * 256 + (g * 4 + tg) * 8 + (j & 1) * 4 + pos;
}
// A-operand fragment-major half offset in x smem (r in 0..63, k in 0..127):
// uint4 per (row-block, kstep) holds [a0, a1, a2, a3] (2 halves each).
DEVINL int ah_off(int r, int k) {
    int rb = r >> 4, g = r & 7, h = (r >> 3) & 1;
    int j = k >> 4, kin = k & 15;
    int hi = kin >> 3;
    int tg = (kin - hi * 8) >> 1;
    int pos = h * 2 + hi * 4 + (kin & 1);
    return (rb * 8 + j) * 256 + (g * 4 + tg) * 8 + pos;
}

// ---------------- precompute kernels ----------------

__global__ void zero_scratch_kernel() {
    int i = blockIdx.x * blockDim.x + threadIdx.x;
    if (i < IN * IN) g_Gf[i] = 0.0f;
    if (i < IN) { g_c[i] = 0.0f; g_sw[i] = 0.0f; }
    if (i < 2)  g_db[i] = 0.0f;
}

__global__ __launch_bounds__(256, 1)
void gram_kernel(const float* __restrict__ w, const float* __restrict__ b) {
    __shared__ float ws[32][IN];
    __shared__ float bs[32];
    const int tid   = threadIdx.x;
    const int jbase = blockIdx.x * 32;

    #pragma unroll
    for (int it = 0; it < 4; ++it) {
        int i  = it * 256 + tid;
        int j  = i >> 5;
        int c4 = (i & 31) * 4;
        float4 v = *reinterpret_cast<const float4*>(w + (size_t)(jbase + j) * IN + c4);
        ws[j][c4 + 0] = f16r(v.x);
        ws[j][c4 + 1] = f16r(v.y);
        ws[j][c4 + 2] = f16r(v.z);
        ws[j][c4 + 3] = f16r(v.w);
    }
    if (tid < 32) bs[tid] = b[jbase + tid];
    __syncthreads();

    // Emit fragment-major fp16 w.
    #pragma unroll
    for (int it = 0; it < 16; ++it) {
        int i = it * 256 + tid;
        int j = i >> 7;                     // local row
        int k = i & 127;
        int R = jbase + j;                  // global row
        g_wh[(size_t)(R >> 7) * (128 * IN) + bh_off(R & 127, k)] =
            __float2half_rn(ws[j][k]);
    }

    const int k     = tid & 127;
    const int lbase = (tid >> 7) * 64;
    float acc[64];
    #pragma unroll
    for (int l = 0; l < 64; ++l) acc[l] = 0.0f;
    float ck = 0.0f, swk = 0.0f;

    for (int j = 0; j < 32; ++j) {
        float wk = ws[j][k];
        #pragma unroll
        for (int l = 0; l < 64; ++l) acc[l] += wk * ws[j][lbase + l];
        ck  += bs[j] * wk;
        swk += wk;
    }
    #pragma unroll
    for (int l = 0; l < 64; ++l)
        atomicAdd(&g_Gf[k * IN + lbase + l], acc[l]);
    if (tid < IN) {
        atomicAdd(&g_c[k], ck);
        atomicAdd(&g_sw[k], swk);
    }
    if (tid < 32) {
        atomicAdd(&g_db[0], bs[tid] * bs[tid]);
        atomicAdd(&g_db[1], bs[tid]);
    }
}

__global__ void pack_G_kernel() {
    int i = blockIdx.x * blockDim.x + threadIdx.x;   // 16384 elements
    if (i < IN * IN) {
        int r = i >> 7, k = i & 127;
        g_Gh[bh_off(r, k)] = __float2half_rn(g_Gf[r * IN + k]);
    }
}

// ---------------- main kernel ----------------

DEVINL void load_x_tile(__half* dst, const float* __restrict__ g, int tid) {
    #pragma unroll
    for (int it = 0; it < (MTILE * 32) / THREADS; ++it) {
        int i  = it * THREADS + tid;
        int r  = i >> 5;
        int c4 = (i & 31) * 4;
        float4 v = *reinterpret_cast<const float4*>(g + (size_t)r * IN + c4);
        float vv[4] = {v.x, v.y, v.z, v.w};
        #pragma unroll
        for (int e = 0; e < 4; ++e)
            dst[ah_off(r, c4 + e)] = __float2half_rn(vv[e]);
    }
}

// Warp-tile 32x32 GEMM, K=128, fp16 m16n8k16.
// a: 2 LDS.128 per kstep. b: 4 LDG.128 per kstep-PAIR (fragment-major, 512B
// warp-contiguous), pipelined jp -> jp+1.
DEVINL void compute_chunk(const __half* __restrict__ xs, const __half* __restrict__ wg,
                          int rb0, int rg0, int lane, float acc[2][4][4]) {
    #pragma unroll
    for (int mt = 0; mt < 2; ++mt)
        #pragma unroll
        for (int nt = 0; nt < 4; ++nt)
            #pragma unroll
            for (int q = 0; q < 4; ++q)
                acc[mt][nt][q] = 0.0f;

    const int lane8 = lane * 8;

    uint4 bcur[4], bnxt[4];
    #pragma unroll
    for (int nt = 0; nt < 4; ++nt)
        bcur[nt] = *reinterpret_cast<const uint4*>(wg + (rg0 + nt) * 1024 + lane8);

    #pragma unroll
    for (int jp = 0; jp < 4; ++jp) {
        if (jp < 3) {
            #pragma unroll
            for (int nt = 0; nt < 4; ++nt)
                bnxt[nt] = *reinterpret_cast<const uint4*>(
                               wg + (rg0 + nt) * 1024 + (jp + 1) * 256 + lane8);
        }
        #pragma unroll
        for (int jo = 0; jo < 2; ++jo) {
            const int j = jp * 2 + jo;
            uint4 a[2];
            #pragma unroll
            for (int mt = 0; mt < 2; ++mt)
                a[mt] = *reinterpret_cast<const uint4*>(
                            xs + ((rb0 + mt) * 8 + j) * 256 + lane8);
            #pragma unroll
            for (int mt = 0; mt < 2; ++mt)
                #pragma unroll
                for (int nt = 0; nt < 4; ++nt)
                    mma_f16(acc[mt][nt], a[mt].x, a[mt].y, a[mt].z, a[mt].w,
                            jo ? bcur[nt].z : bcur[nt].x,
                            jo ? bcur[nt].w : bcur[nt].y);
        }
        #pragma unroll
        for (int nt = 0; nt < 4; ++nt) bcur[nt] = bnxt[nt];
    }
}

__global__ __launch_bounds__(THREADS, 2)
void fused_lin_inorm_kernel(const float* __restrict__ x,
                            const float* __restrict__ y,
                            const float* __restrict__ lb,
                            const float* __restrict__ nw,
                            const float* __restrict__ nb,
                            float* __restrict__ out) {
    __shared__ float sm[TOTAL_F];
    const int tid  = threadIdx.x;
    const int wid  = tid >> 5;
    const int lane = tid & 31;
    const int g    = lane >> 2;
    const int tig  = lane & 3;
    const int m0   = (wid >> 2) * 32;
    const int n0   = (wid & 3) * 32;
    const int rb0  = m0 >> 4;
    const int rg0  = n0 >> 3;
    const size_t row0 = (size_t)blockIdx.x * MTILE;

    __half* xs = reinterpret_cast<__half*>(sm + X_OFF);
    float*  st = sm + STAGE_OFF + wid * (32 * SSTR);   // warp-private stage

    if (tid < MTILE) sm[SQ_OFF + tid] = 0.0f;
    load_x_tile(xs, x + row0 * IN, tid);
    __syncthreads();

    // Per-row mean and x'.c from fp16-rounded global x (natural-order coeffs).
    if (tid < MTILE) {
        const float* xr = x + (row0 + tid) * IN;
        float dm = 0.0f, dc = 0.0f;
        #pragma unroll 8
        for (int k4 = 0; k4 < 32; ++k4) {
            float4 xv = __ldg(reinterpret_cast<const float4*>(xr + k4 * 4));
            float4 sv = __ldg(reinterpret_cast<const float4*>(g_sw + k4 * 4));
            float4 cv = __ldg(reinterpret_cast<const float4*>(g_c + k4 * 4));
            float x0 = f16r(xv.x), x1 = f16r(xv.y), x2 = f16r(xv.z), x3 = f16r(xv.w);
            dm += x0 * sv.x + x1 * sv.y + x2 * sv.z + x3 * sv.w;
            dc += x0 * cv.x + x1 * cv.y + x2 * cv.z + x3 * cv.w;
        }
        sm[MEAN_OFF + tid] = (dm + g_db[1]) * (1.0f / OUT);
        sm[DOTC_OFF + tid] = dc;
    }

    // ---- stats chunk: Z = x' @ Ghat ; rsq = sum Z .* x' per row ----
    {
        float acc[2][4][4];
        compute_chunk(xs, g_Gh, rb0, rg0, lane, acc);

        float rsq[4] = {0.f, 0.f, 0.f, 0.f};
        #pragma unroll
        for (int mt = 0; mt < 2; ++mt)
            #pragma unroll
            for (int h = 0; h < 2; ++h) {
                const int r = m0 + mt * 16 + h * 8 + g;
                #pragma unroll
                for (int nt = 0; nt < 4; ++nt)
                    #pragma unroll
                    for (int p = 0; p < 2; ++p) {
                        int col = n0 + nt * 8 + tig * 2 + p;
                        rsq[mt * 2 + h] += acc[mt][nt][h * 2 + p] *
                                           __half2float(xs[ah_off(r, col)]);
                    }
            }
        #pragma unroll
        for (int j = 0; j < 4; ++j) {
            rsq[j] += __shfl_xor_sync(0xffffffffu, rsq[j], 1);
            rsq[j] += __shfl_xor_sync(0xffffffffu, rsq[j], 2);
        }
        if (tig == 0) {
            #pragma unroll
            for (int j = 0; j < 4; ++j) {
                int r = m0 + (j >> 1) * 16 + (j & 1) * 8 + g;
                atomicAdd(&sm[SQ_OFF + r], rsq[j]);
            }
        }
    }
    __syncthreads();

    if (tid < MTILE) {
        float sumsq = sm[SQ_OFF + tid] + 2.0f * sm[DOTC_OFF + tid] + g_db[0];
        float mean  = sm[MEAN_OFF + tid];
        float var   = sumsq * (1.0f / OUT) - mean * mean;
        sm[ISTD_OFF + tid] = rsqrtf(var + 1e-5f);
    }
    __syncthreads();

    // Per-lane epilogue row constants (iteration j covers rows j*4 + (lane>>3)).
    const int rl = lane >> 3;       // 0..3
    const int cl = (lane & 7) * 4;  // 0,4,...,28
    float meanv[8], istdv[8];
    #pragma unroll
    for (int j = 0; j < 8; ++j) {
        int r = m0 + j * 4 + rl;
        meanv[j] = sm[MEAN_OFF + r];
        istdv[j] = sm[ISTD_OFF + r];
    }

    // ---------------- main loop: 16 chunks, NO CTA barriers ----------------
    #pragma unroll 1
    for (int ch = 0; ch < NCHUNKS; ++ch) {
        float acc[2][4][4];
        compute_chunk(xs, g_wh + (size_t)ch * NCHUNK * IN, rb0, rg0, lane, acc);

        // Stage the 32x32 acc tile into warp-private smem (conflict-free).
        #pragma unroll
        for (int mt = 0; mt < 2; ++mt)
            #pragma unroll
            for (int h = 0; h < 2; ++h)
                #pragma unroll
                for (int nt = 0; nt < 4; ++nt) {
                    float2 v = make_float2(acc[mt][nt][h * 2 + 0], acc[mt][nt][h * 2 + 1]);
                    *reinterpret_cast<float2*>(
                        st + (mt * 16 + h * 8 + g) * SSTR + nt * 8 + tig * 2) = v;
                }
        __syncwarp();

        // Coalesced readback + fused epilogue (float4, 4 lines/instr).
        const int cbase = ch * NCHUNK + n0;
        float4 lbv = __ldg(reinterpret_cast<const float4*>(lb + cbase + cl));
        float4 nwv = __ldg(reinterpret_cast<const float4*>(nw + cbase + cl));
        float4 nbv = __ldg(reinterpret_cast<const float4*>(nb + cbase + cl));

        #pragma unroll
        for (int j = 0; j < 8; ++j) {
            const int r = j * 4 + rl;
            float4 v = *reinterpret_cast<const float4*>(st + r * SSTR + cl);
            const size_t grow = row0 + (size_t)(m0 + r);
            float4 yv = __ldg(reinterpret_cast<const float4*>(y + grow * OUT + cbase + cl));
            const float mean = meanv[j], istd = istdv[j];
            float4 ov;
            float nm;
            nm = ((v.x + lbv.x) - mean) * istd * nwv.x + nbv.x; ov.x = (nm + yv.x) * yv.x;
            nm = ((v.y + lbv.y) - mean) * istd * nwv.y + nbv.y; ov.y = (nm + yv.y) * yv.y;
            nm = ((v.z + lbv.z) - mean) * istd * nwv.z + nbv.z; ov.z = (nm + yv.z) * yv.z;
            nm = ((v.w + lbv.w) - mean) * istd * nwv.w + nbv.w; ov.w = (nm + yv.w) * yv.w;
            *reinterpret_cast<float4*>(out + grow * OUT + cbase + cl) = ov;
        }
        __syncwarp();   // stage buffer reusable next chunk
    }
}

extern "C" void kernel_launch(void* const* d_in, const int* in_sizes, int n_in,
                              void* d_out, int out_size) {
    (void)n_in; (void)out_size;
    const float* x  = (const float*)d_in[0];
    const float* y  = (const float*)d_in[1];
    const float* w  = (const float*)d_in[2];
    const float* lb = (const float*)d_in[3];
    const float* nw = (const float*)d_in[4];
    const float* nb = (const float*)d_in[5];
    float* out = (float*)d_out;

    const int rows = in_sizes[0] / IN;   // 32768
    const int grid = rows / MTILE;       // 512

    zero_scratch_kernel<<<64, 256>>>();
    gram_kernel<<<OUT / 32, 256>>>(w, lb);
    pack_G_kernel<<<64, 256>>>();
    fused_lin_inorm_kernel<<<grid, THREADS>>>(x, y, lb, nw, nb, out);
}